// round 11
// baseline (speedup 1.0000x reference)
#include <cuda_runtime.h>
#include <math.h>

#define N_NODES 100000
#define HID 128
#define NF (N_NODES * HID)   // 12,800,000
#define KG 20
#define E_MAX 3200000

// Persistent scratch (allocation-free requirement -> __device__ globals)
__device__ float d_g[NF];          // features g = h @ W (unscaled)
__device__ float d_h[NF];          // layer output (post-relu)
__device__ float d_dis[N_NODES];   // rsqrt(deg+1)
__device__ int   d_deg[N_NODES];
__device__ int   d_off[N_NODES + 1];
__device__ int   d_cursor[N_NODES];
__device__ int   d_csr[E_MAX];     // src indices grouped by dst

// Packed fp32x2 FMA (Blackwell): 2 fp32 MACs per instruction.
#define FMA2(a, x, w) \
    asm("fma.rn.f32x2 %0, %1, %2, %0;" : "+l"(a) : "l"(x), "l"(w))

// ---------------------------------------------------------------------------
// CSR build: histogram -> scan (+dis) -> fill
// ---------------------------------------------------------------------------
__global__ void k_deg_zero() {
    int i = blockIdx.x * blockDim.x + threadIdx.x;
    if (i < N_NODES) d_deg[i] = 0;
}

__global__ void k_deg_count(const int* __restrict__ dst, int E) {
    int e = blockIdx.x * blockDim.x + threadIdx.x;
    if (e < E) atomicAdd(&d_deg[dst[e]], 1);
}

// Single-block exclusive scan over N_NODES degrees; also writes dis = rsqrt(deg+1).
__global__ void __launch_bounds__(1024) k_scan() {
    const int T = 1024;
    const int CH = (N_NODES + T - 1) / T;   // 98
    int tid = threadIdx.x;
    int beg = tid * CH;
    int end = beg + CH; if (end > N_NODES) end = N_NODES;

    int s = 0;
    for (int i = beg; i < end; i++) s += d_deg[i];

    __shared__ int wsum[32];
    int lane = tid & 31, wid = tid >> 5;
    int v = s;
#pragma unroll
    for (int o = 1; o < 32; o <<= 1) {
        int t = __shfl_up_sync(0xffffffffu, v, o);
        if (lane >= o) v += t;
    }
    if (lane == 31) wsum[wid] = v;
    __syncthreads();
    if (wid == 0) {
        int w = wsum[lane];
#pragma unroll
        for (int o = 1; o < 32; o <<= 1) {
            int t = __shfl_up_sync(0xffffffffu, w, o);
            if (lane >= o) w += t;
        }
        wsum[lane] = w;
    }
    __syncthreads();

    int run = v - s + (wid ? wsum[wid - 1] : 0);   // exclusive prefix
    for (int i = beg; i < end; i++) {
        int dg = d_deg[i];
        d_off[i] = run;
        d_cursor[i] = run;
        d_dis[i] = rsqrtf((float)(dg + 1));        // +1 self-loop
        run += dg;
    }
    if (tid == T - 1) d_off[N_NODES] = run;
}

__global__ void k_fill(const int* __restrict__ src, const int* __restrict__ dst,
                       int E) {
    int e = blockIdx.x * blockDim.x + threadIdx.x;
    if (e < E) {
        int d = dst[e];
        int pos = atomicAdd(&d_cursor[d], 1);
        d_csr[pos] = src[e];
    }
}

// ---------------------------------------------------------------------------
// GEMM (packed f32x2): d_g = A @ W   (M x 128 @ 128 x 128), no dis scaling.
// Tile: 64 rows x 128 cols, 256 threads. Xt is k-major so a LDS64 fetches a
// packed row-pair; each thread owns 4 row-pairs x 4 cols of packed accumulators.
// ---------------------------------------------------------------------------
__global__ void __launch_bounds__(256) k_gemm(const float* __restrict__ A,
                                              const float* __restrict__ W,
                                              int M, int useH) {
    __shared__ float Ws[32 * 128];  // [k][c]      16 KB
    __shared__ float Xt[32 * 66];   // [k][row], stride 66 (conflict padding)
    const float* Ap = useH ? (const float*)d_h : A;

    int tid  = threadIdx.x;
    int warp = tid >> 5;
    int lane = tid & 31;
    int rowBase = blockIdx.x * 64;

    unsigned long long acc[4][4];   // [rowpair][col]; 0ull == {+0.f, +0.f}
#pragma unroll
    for (int i = 0; i < 4; i++)
#pragma unroll
        for (int j = 0; j < 4; j++) acc[i][j] = 0ull;

    for (int kc = 0; kc < 4; kc++) {
#pragma unroll
        for (int i = 0; i < 16; i++) {
            int idx = tid + i * 256;
            Ws[idx] = W[kc * 4096 + idx];
        }
#pragma unroll
        for (int i = 0; i < 2; i++) {
            int f = tid + i * 256;          // 0..511 float4s
            int r = f >> 3, c4 = f & 7;
            int gr = rowBase + r;
            float4 v = make_float4(0.f, 0.f, 0.f, 0.f);
            if (gr < M) v = *(const float4*)&Ap[gr * 128 + kc * 32 + c4 * 4];
            int kb = c4 * 4;
            Xt[(kb + 0) * 66 + r] = v.x;
            Xt[(kb + 1) * 66 + r] = v.y;
            Xt[(kb + 2) * 66 + r] = v.z;
            Xt[(kb + 3) * 66 + r] = v.w;
        }
        __syncthreads();

#pragma unroll 4
        for (int k = 0; k < 32; k++) {
            float4 w = *(const float4*)&Ws[k * 128 + lane * 4];
            unsigned long long wd0, wd1, wd2, wd3;
            asm("mov.b64 %0, {%1, %1};" : "=l"(wd0) : "f"(w.x));
            asm("mov.b64 %0, {%1, %1};" : "=l"(wd1) : "f"(w.y));
            asm("mov.b64 %0, {%1, %1};" : "=l"(wd2) : "f"(w.z));
            asm("mov.b64 %0, {%1, %1};" : "=l"(wd3) : "f"(w.w));
            const float* xr = &Xt[k * 66 + warp * 8];
            unsigned long long x0 = *(const unsigned long long*)(xr + 0);
            unsigned long long x1 = *(const unsigned long long*)(xr + 2);
            unsigned long long x2 = *(const unsigned long long*)(xr + 4);
            unsigned long long x3 = *(const unsigned long long*)(xr + 6);
            FMA2(acc[0][0], x0, wd0); FMA2(acc[0][1], x0, wd1);
            FMA2(acc[0][2], x0, wd2); FMA2(acc[0][3], x0, wd3);
            FMA2(acc[1][0], x1, wd0); FMA2(acc[1][1], x1, wd1);
            FMA2(acc[1][2], x1, wd2); FMA2(acc[1][3], x1, wd3);
            FMA2(acc[2][0], x2, wd0); FMA2(acc[2][1], x2, wd1);
            FMA2(acc[2][2], x2, wd2); FMA2(acc[2][3], x2, wd3);
            FMA2(acc[3][0], x3, wd0); FMA2(acc[3][1], x3, wd1);
            FMA2(acc[3][2], x3, wd2); FMA2(acc[3][3], x3, wd3);
        }
        __syncthreads();
    }

#pragma unroll
    for (int rp = 0; rp < 4; rp++) {
        int r0 = rowBase + warp * 8 + rp * 2;
        float lo[4], hi[4];
#pragma unroll
        for (int c = 0; c < 4; c++)
            asm("mov.b64 {%0, %1}, %2;" : "=f"(lo[c]), "=f"(hi[c])
                                        : "l"(acc[rp][c]));
        if (r0 < M)
            *(float4*)&d_g[r0 * 128 + lane * 4] =
                make_float4(lo[0], lo[1], lo[2], lo[3]);
        if (r0 + 1 < M)
            *(float4*)&d_g[(r0 + 1) * 128 + lane * 4] =
                make_float4(hi[0], hi[1], hi[2], hi[3]);
    }
}

// ---------------------------------------------------------------------------
// Fused CSR gather + finalize: one warp per node, lane l = float4 column l.
//   h[r] = relu( dis[r] * ( sum_e dis[src_e]*g[src_e] + dis[r]*g[r] ) + b )
// ---------------------------------------------------------------------------
__global__ void __launch_bounds__(256) k_gather(const float* __restrict__ b) {
    int w = (blockIdx.x * 256 + threadIdx.x) >> 5;
    if (w >= N_NODES) return;
    int lane = threadIdx.x & 31;
    const float4* __restrict__ g4 = (const float4*)d_g;

    float sr = d_dis[w];
    float4 gv = g4[w * 32 + lane];     // self-loop term
    float4 acc;
    acc.x = sr * gv.x; acc.y = sr * gv.y;
    acc.z = sr * gv.z; acc.w = sr * gv.w;

    int beg = d_off[w], end = d_off[w + 1];
    for (int e0 = beg; e0 < end; e0 += 32) {
        int n = end - e0; if (n > 32) n = 32;
        int idx = 0; float nrm = 0.f;
        if (lane < n) { idx = d_csr[e0 + lane]; nrm = d_dis[idx]; }
        int j = 0;
        for (; j + 4 <= n; j += 4) {
            int s0 = __shfl_sync(0xffffffffu, idx, j);
            int s1 = __shfl_sync(0xffffffffu, idx, j + 1);
            int s2 = __shfl_sync(0xffffffffu, idx, j + 2);
            int s3 = __shfl_sync(0xffffffffu, idx, j + 3);
            float f0 = __shfl_sync(0xffffffffu, nrm, j);
            float f1 = __shfl_sync(0xffffffffu, nrm, j + 1);
            float f2 = __shfl_sync(0xffffffffu, nrm, j + 2);
            float f3 = __shfl_sync(0xffffffffu, nrm, j + 3);
            float4 v0 = g4[s0 * 32 + lane];
            float4 v1 = g4[s1 * 32 + lane];
            float4 v2 = g4[s2 * 32 + lane];
            float4 v3 = g4[s3 * 32 + lane];
            acc.x = fmaf(f0, v0.x, fmaf(f1, v1.x, fmaf(f2, v2.x, fmaf(f3, v3.x, acc.x))));
            acc.y = fmaf(f0, v0.y, fmaf(f1, v1.y, fmaf(f2, v2.y, fmaf(f3, v3.y, acc.y))));
            acc.z = fmaf(f0, v0.z, fmaf(f1, v1.z, fmaf(f2, v2.z, fmaf(f3, v3.z, acc.z))));
            acc.w = fmaf(f0, v0.w, fmaf(f1, v1.w, fmaf(f2, v2.w, fmaf(f3, v3.w, acc.w))));
        }
        for (; j < n; j++) {
            int s = __shfl_sync(0xffffffffu, idx, j);
            float f = __shfl_sync(0xffffffffu, nrm, j);
            float4 v = g4[s * 32 + lane];
            acc.x = fmaf(f, v.x, acc.x); acc.y = fmaf(f, v.y, acc.y);
            acc.z = fmaf(f, v.z, acc.z); acc.w = fmaf(f, v.w, acc.w);
        }
    }

    float4 bb = ((const float4*)b)[lane];
    float4 o;
    o.x = fmaxf(fmaf(sr, acc.x, bb.x), 0.f);
    o.y = fmaxf(fmaf(sr, acc.y, bb.y), 0.f);
    o.z = fmaxf(fmaf(sr, acc.z, bb.z), 0.f);
    o.w = fmaxf(fmaf(sr, acc.w, bb.w), 0.f);
    ((float4*)d_h)[w * 32 + lane] = o;
}

// ---------------------------------------------------------------------------
// MDN heads: per node 60 logits (20 pi / 20 mu / 20 log_sigma), softmax on pi.
// Block = 256 = 4 groups x 64 threads; each group handles 4 nodes.
// ---------------------------------------------------------------------------
__global__ void __launch_bounds__(256) k_heads(
    const float* __restrict__ piW, const float* __restrict__ pib,
    const float* __restrict__ muW, const float* __restrict__ mub,
    const float* __restrict__ lsW, const float* __restrict__ lsb,
    float* __restrict__ out) {
    __shared__ float hs[16 * 128];  // 8 KB
    int tid = threadIdx.x;
    int nodeBase = blockIdx.x * 16;
#pragma unroll
    for (int i = 0; i < 8; i++) {
        int idx = tid + i * 256;
        hs[idx] = d_h[nodeBase * 128 + idx];
    }
    __syncthreads();

    int grp = tid >> 6;
    int c   = tid & 63;
    if (c >= 60) return;  // only lanes 60..63 of 2nd warp exit; 1st warp intact

    const float* wp;
    float bias;
    if (c < 20)      { wp = piW + c;        bias = pib[c];      }
    else if (c < 40) { wp = muW + (c - 20); bias = mub[c - 20]; }
    else             { wp = lsW + (c - 40); bias = lsb[c - 40]; }

    const float* h0 = &hs[grp * 4 * 128];
    float z0 = bias, z1 = bias, z2 = bias, z3 = bias;
#pragma unroll 8
    for (int k = 0; k < 128; k++) {
        float w = __ldg(wp + k * KG);
        z0 = fmaf(h0[k],       w, z0);
        z1 = fmaf(h0[128 + k], w, z1);
        z2 = fmaf(h0[256 + k], w, z2);
        z3 = fmaf(h0[384 + k], w, z3);
    }
    float z[4] = {z0, z1, z2, z3};
    int nodeG = nodeBase + grp * 4;

    if (c < 32) {
        // entire first warp of the group: pi softmax reductions.
#pragma unroll
        for (int j = 0; j < 4; j++) {
            float m = (c < 20) ? z[j] : -INFINITY;
#pragma unroll
            for (int o = 16; o; o >>= 1)
                m = fmaxf(m, __shfl_xor_sync(0xffffffffu, m, o));
            float e = (c < 20) ? expf(z[j] - m) : 0.f;
            float ss = e;
#pragma unroll
            for (int o = 16; o; o >>= 1)
                ss += __shfl_xor_sync(0xffffffffu, ss, o);
            if (c < 20) out[(nodeG + j) * KG + c] = e / ss;
        }
    }
    if (c >= 20 && c < 40) {
#pragma unroll
        for (int j = 0; j < 4; j++)
            out[N_NODES * KG + (nodeG + j) * KG + (c - 20)] = z[j];
    } else if (c >= 40) {
#pragma unroll
        for (int j = 0; j < 4; j++)
            out[2 * N_NODES * KG + (nodeG + j) * KG + (c - 40)] = z[j];
    }
}

// ---------------------------------------------------------------------------
extern "C" void kernel_launch(void* const* d_in, const int* in_sizes, int n_in,
                              void* d_out, int out_size) {
    const float* x   = (const float*)d_in[0];
    const int*   ei  = (const int*)d_in[1];
    const float* W1  = (const float*)d_in[2];
    const float* b1  = (const float*)d_in[3];
    const float* W2  = (const float*)d_in[4];
    const float* b2  = (const float*)d_in[5];
    const float* piW = (const float*)d_in[6];
    const float* pib = (const float*)d_in[7];
    const float* muW = (const float*)d_in[8];
    const float* mub = (const float*)d_in[9];
    const float* lsW = (const float*)d_in[10];
    const float* lsb = (const float*)d_in[11];
    float* out = (float*)d_out;

    const int E = in_sizes[1] / 2;
    const int* src = ei;
    const int* dst = ei + E;
    const int M = N_NODES;

    const int gN    = (N_NODES + 255) / 256;
    const int gE    = (E + 255) / 256;
    const int gGemm = (M + 63) / 64;                 // 1563
    const int gGath = (N_NODES * 32 + 255) / 256;    // 12500
    const int gHead = N_NODES / 16;                  // 6250

    // Host-side resources created once (no device memory involved).
    static cudaStream_t s2 = nullptr;
    static cudaEvent_t evFork = nullptr, evCsr = nullptr;
    if (s2 == nullptr) {
        cudaStreamCreateWithFlags(&s2, cudaStreamNonBlocking);
        cudaEventCreateWithFlags(&evFork, cudaEventDisableTiming);
        cudaEventCreateWithFlags(&evCsr, cudaEventDisableTiming);
    }

    // Fork: CSR build (degree -> scan+dis -> fill) on s2, GEMM1 on main stream.
    cudaEventRecord(evFork, 0);
    cudaStreamWaitEvent(s2, evFork, 0);
    k_deg_zero<<<gN, 256, 0, s2>>>();
    k_deg_count<<<gE, 256, 0, s2>>>(dst, E);
    k_scan<<<1, 1024, 0, s2>>>();
    k_fill<<<gE, 256, 0, s2>>>(src, dst, E);
    cudaEventRecord(evCsr, s2);

    k_gemm<<<gGemm, 256>>>(x, W1, M, 0);        // d_g = x @ W1 (concurrent w/ CSR)

    // Join, then the serialized tail.
    cudaStreamWaitEvent(0, evCsr, 0);
    k_gather<<<gGath, 256>>>(b1);               // d_h = relu(dis*(Σ dis_s g_s + dis_r g_r)+b1)
    k_gemm<<<gGemm, 256>>>(nullptr, W2, M, 1);
    k_gather<<<gGath, 256>>>(b2);
    k_heads<<<gHead, 256>>>(piW, pib, muW, mub, lsW, lsb, out);
}